// round 5
// baseline (speedup 1.0000x reference)
#include <cuda_runtime.h>
#include <math.h>

#define B 8
#define C 64
#define L 2048
#define CS 256
#define HD 64
#define TD 16
#define HH 32
#define FL 8
#define NT 25
#define NTOT (B*CS*L)          // 4,194,304
#define NCL  (B*C*L)           // 1,048,576

// ---------------- scratch (device globals; no allocs allowed) ----------------
__device__ float g_stacked[NTOT];
__device__ float g_y[NTOT];
__device__ float g_ytmp[NTOT];
__device__ float g_s[6][NTOT];
__device__ float g_h1[B*HD*L];
__device__ float g_h2[B*HD*L];
__device__ float g_apA[NCL];
__device__ float g_apB[NCL];
__device__ float g_maxv[B*C];
__device__ float g_lof[FL], g_hif[FL];
__device__ float g_gamma[NT*HD], g_beta[NT*HD];
__device__ float g_part[B*64];

__device__ __forceinline__ float gelu(float x){
    return 0.5f * x * (1.0f + erff(x * 0.70710678118654752440f));
}

// ---------------- tiled conv1d (k=3, pad=1) ----------------
// Grid: (L/64, B, OTOT/64). Block 256. Each block: 64 out-ch x 64 l.
// Thread: 4 o x 4 l micro-tile. Dynamic smem: x tile [64][68] + w chunk [64][64*3].
template<int IC, int OTOT, bool FILM, bool GELU_OUT>
__global__ void __launch_bounds__(256) conv_k(
    const float* __restrict__ in, const float* __restrict__ w,
    const float* __restrict__ bias, float* __restrict__ out,
    const float* __restrict__ gamma, const float* __restrict__ beta)
{
    extern __shared__ float smem[];
    float* sx = smem;               // 64*68
    float* sw = smem + 64*68;       // 64*192

    const int tid = threadIdx.x;
    const int l0  = blockIdx.x * 64;
    const int b   = blockIdx.y;
    const int o0  = blockIdx.z * 64;
    const int lg  = tid & 15;       // 0..15 -> l group
    const int og  = tid >> 4;       // 0..15 -> o group
    const int lbase  = lg * 4;
    const int olocal = og * 4;

    float acc[4][4] = {};

    for (int ic0 = 0; ic0 < IC; ic0 += 64) {
        __syncthreads();
        // stage input tile [64][66] (l0-1 .. l0+64), zero at boundaries
        const float* inb = in + ((size_t)b * IC + ic0) * L;
        for (int idx = tid; idx < 64*66; idx += 256) {
            int ic = idx / 66, ll = idx % 66;
            int gl = l0 - 1 + ll;
            sx[ic*68 + ll] = (gl >= 0 && gl < L) ? inb[ic*L + gl] : 0.0f;
        }
        // stage weight chunk [64 o][64 ic][3]
        const float* wb = w + ((size_t)o0 * IC + ic0) * 3;
        for (int idx = tid; idx < 64*192; idx += 256) {
            int oo = idx / 192, r = idx % 192;
            sw[oo*192 + r] = wb[(size_t)oo * IC * 3 + r];
        }
        __syncthreads();

        #pragma unroll 2
        for (int ic = 0; ic < 64; ic++) {
            const float4* xr = (const float4*)(sx + ic*68);
            float4 xa = xr[lg];
            float4 xb = xr[lg + 1];
            float xv[6] = {xa.x, xa.y, xa.z, xa.w, xb.x, xb.y};
            #pragma unroll
            for (int oo = 0; oo < 4; oo++) {
                const float* wp = sw + (olocal + oo)*192 + ic*3;
                float w0 = wp[0], w1 = wp[1], w2 = wp[2];
                #pragma unroll
                for (int j = 0; j < 4; j++)
                    acc[oo][j] += w0*xv[j] + w1*xv[j+1] + w2*xv[j+2];
            }
        }
    }

    // epilogue: bias (+ FiLM) (+ GELU), vectorized store
    #pragma unroll
    for (int oo = 0; oo < 4; oo++) {
        int o = o0 + olocal + oo;
        float bs = bias[o];
        float ga = 0.f, be = 0.f;
        if (FILM) { ga = gamma[o - o0]; be = beta[o - o0]; }
        float4 r;
        float* rv = &r.x;
        #pragma unroll
        for (int j = 0; j < 4; j++) {
            float v = acc[oo][j] + bs;
            if (FILM)     v = (1.0f + ga) * v + be;
            if (GELU_OUT) v = gelu(v);
            rv[j] = v;
        }
        *(float4*)(out + ((size_t)b * OTOT + o) * L + l0 + lbase) = r;
    }
}

// ---------------- RK stage combine: out = y + h * sum(c_j * s_j) ----------------
template<int NS>
__global__ void combine_k(float4* __restrict__ out, const float4* __restrict__ y, float h,
    const float4* s0, float c0, const float4* s1, float c1, const float4* s2, float c2,
    const float4* s3, float c3, const float4* s4, float c4)
{
    int i = blockIdx.x * blockDim.x + threadIdx.x;
    if (i >= NTOT/4) return;
    float4 acc = y[i];
    const float4* ss[5] = {s0, s1, s2, s3, s4};
    float cc[5] = {c0, c1, c2, c3, c4};
    #pragma unroll
    for (int j = 0; j < NS; j++) {
        float4 v = ss[j][i];
        float a = h * cc[j];
        acc.x += a*v.x; acc.y += a*v.y; acc.z += a*v.z; acc.w += a*v.w;
    }
    out[i] = acc;
}

// ---------------- time embedding: all 25 (gamma,beta) pairs ----------------
__global__ void temb_k(const float* __restrict__ tw1, const float* __restrict__ tb1,
                       const float* __restrict__ tw2, const float* __restrict__ tb2,
                       const float* __restrict__ cw,  const float* __restrict__ cb)
{
    int idx = blockIdx.x;       // 0..24
    int j = threadIdx.x;        // 0..127
    float t;
    if (idx == 24) t = 1.0f;
    else {
        const float off[6] = {0.0f, 0.2f, 0.3f, 0.8f, 8.0f/9.0f, 1.0f};
        t = (idx / 6) * 0.25f + off[idx % 6] * 0.25f;
    }
    __shared__ float e1[TD], te[TD];
    if (j < TD) e1[j] = gelu(t * tw1[j] + tb1[j]);
    __syncthreads();
    if (j < TD) {
        float s = tb2[j];
        for (int e = 0; e < TD; e++) s += e1[e] * tw2[j*TD + e];
        te[j] = s;
    }
    __syncthreads();
    float s = cb[j];
    for (int d = 0; d < TD; d++) s += te[d] * cw[j*TD + d];
    if (j < HD) g_gamma[idx*HD + j] = s;
    else        g_beta[idx*HD + (j - HD)] = s;
}

// ---------------- max over L per (b,c) ----------------
__global__ void maxred_k(const float* __restrict__ in)
{
    int bc = blockIdx.x;
    const float* p = in + (size_t)bc * L;
    float m = -INFINITY;
    for (int i = threadIdx.x; i < L; i += 256) m = fmaxf(m, p[i]);
    __shared__ float sm[8];
    #pragma unroll
    for (int o = 16; o > 0; o >>= 1) m = fmaxf(m, __shfl_xor_sync(0xffffffffu, m, o));
    if ((threadIdx.x & 31) == 0) sm[threadIdx.x >> 5] = m;
    __syncthreads();
    if (threadIdx.x == 0) {
        float r = sm[0];
        for (int w = 1; w < 8; w++) r = fmaxf(r, sm[w]);
        g_maxv[bc] = r;
    }
}

// ---------------- dywan MLP -> normalized filters (single block) ----------------
__global__ void dywan_k(const float* __restrict__ sw1, const float* __restrict__ sb1,
                        const float* __restrict__ sw2, const float* __restrict__ sb2,
                        const float* __restrict__ sw3, const float* __restrict__ sb3)
{
    __shared__ float feat[B*HH], g2[B*HH], raw[B*16], nrm[B*2];
    int tid = threadIdx.x;
    if (tid < B*HH) {
        int b = tid / HH, h = tid % HH;
        float s = sb1[h];
        for (int c = 0; c < C; c++) s += g_maxv[b*C + c] * sw1[h*C + c];
        feat[tid] = gelu(s);
    }
    __syncthreads();
    if (tid < B*HH) {
        int b = tid / HH, h = tid % HH;
        float s = sb2[h];
        for (int e = 0; e < HH; e++) s += feat[b*HH + e] * sw2[h*HH + e];
        g2[tid] = gelu(s);
    }
    __syncthreads();
    if (tid < B*16) {
        int b = tid / 16, jj = tid % 16;
        float s = sb3[jj];
        for (int e = 0; e < HH; e++) s += g2[b*HH + e] * sw3[jj*HH + e];
        raw[tid] = s;
    }
    __syncthreads();
    if (tid < B*2) {
        int b = tid / 2, half = tid % 2;
        float s = 0.f;
        for (int k = 0; k < FL; k++) { float v = raw[b*16 + half*8 + k]; s += v*v; }
        nrm[tid] = 1.0f / sqrtf(s);
    }
    __syncthreads();
    if (tid < 16) {
        int half = tid / 8, k = tid % 8;
        float s = 0.f;
        for (int b = 0; b < B; b++) s += raw[b*16 + half*8 + k] * nrm[b*2 + half];
        s *= (1.0f / B);
        if (half == 0) g_lof[k] = s; else g_hif[k] = s;
    }
}

// ---------------- depthwise wavelet conv (reflect pad 3/4, 8 taps) ----------------
__global__ void wconv_k(const float* __restrict__ in, float* __restrict__ newap, int lev)
{
    int idx = blockIdx.x * blockDim.x + threadIdx.x;
    if (idx >= NCL) return;
    int l  = idx % L;
    int bc = idx / L;
    int b = bc / C, c = bc % C;
    const float* ap = in + (size_t)bc * L;
    float lo = 0.f, hi = 0.f;
    #pragma unroll
    for (int k = 0; k < FL; k++) {
        int src = l + k - 3;
        src = src < 0 ? -src : (src >= L ? 2*L - 2 - src : src);
        float v = ap[src];
        lo += g_lof[k] * v;
        hi += g_hif[k] * v;
    }
    newap[idx] = lo;
    g_stacked[(size_t)b*CS*L + ((size_t)(lev+1)*C + c)*L + l] = hi;
}

// ---------------- copy x into stacked[:, 0:C] ----------------
__global__ void cpx_k(const float* __restrict__ x)
{
    int idx = blockIdx.x * blockDim.x + threadIdx.x;
    if (idx >= NCL) return;
    int b = idx / (C*L);
    int r = idx % (C*L);
    g_stacked[(size_t)b*CS*L + r] = x[idx];
}

// ---------------- ecloss partial + final ----------------
__global__ void ecl1_k(const float* __restrict__ dx)
{
    int b = blockIdx.x / 64, part = blockIdx.x % 64;
    const int CH = CS*L/64;  // 8192
    const float* sp = g_stacked + (size_t)b*CS*L + (size_t)part*CH;
    const float* dp = dx        + (size_t)b*CS*L + (size_t)part*CH;
    float s = 0.f;
    for (int i = threadIdx.x; i < CH; i += 256) s += sp[i] * dp[i];
    __shared__ float sm[8];
    #pragma unroll
    for (int o = 16; o > 0; o >>= 1) s += __shfl_xor_sync(0xffffffffu, s, o);
    if ((threadIdx.x & 31) == 0) sm[threadIdx.x >> 5] = s;
    __syncthreads();
    if (threadIdx.x == 0) {
        float t = 0.f;
        for (int w = 0; w < 8; w++) t += sm[w];
        g_part[blockIdx.x] = t;
    }
}

__global__ void ecl2_k(float* __restrict__ out)
{
    __shared__ float inner[B];
    if (threadIdx.x < B) {
        float s = 0.f;
        for (int p = 0; p < 64; p++) s += g_part[threadIdx.x*64 + p];
        inner[threadIdx.x] = s;
    }
    __syncthreads();
    if (threadIdx.x == 0) {
        float e = 0.f;
        for (int b = 0; b < B; b++) e += inner[b] * inner[b];
        out[4*NCL] = e / (float)B;
    }
}

// ---------------- output permute: (yl,yh0,yh1,yh2) layout ----------------
__global__ void perm_k(float* __restrict__ out)
{
    int idx = blockIdx.x * blockDim.x + threadIdx.x;
    if (idx >= 4*NCL) return;
    int g = idx / NCL;
    int r = idx % NCL;
    int b = r / (C*L);
    int cl = r % (C*L);
    int c = cl / L, l = cl % L;
    out[idx] = g_y[(size_t)b*CS*L + ((size_t)(g*C + c))*L + l];
}

// ---------------- host orchestration ----------------
extern "C" void kernel_launch(void* const* d_in, const int* in_sizes, int n_in,
                              void* d_out, int out_size)
{
    const float* x   = (const float*)d_in[0];
    const float* sw1 = (const float*)d_in[1];
    const float* sb1 = (const float*)d_in[2];
    const float* sw2 = (const float*)d_in[3];
    const float* sb2 = (const float*)d_in[4];
    const float* sw3 = (const float*)d_in[5];
    const float* sb3 = (const float*)d_in[6];
    const float* tw1 = (const float*)d_in[7];
    const float* tb1 = (const float*)d_in[8];
    const float* tw2 = (const float*)d_in[9];
    const float* tb2 = (const float*)d_in[10];
    const float* cw  = (const float*)d_in[11];
    const float* cb  = (const float*)d_in[12];
    const float* k1  = (const float*)d_in[13];
    const float* kb1 = (const float*)d_in[14];
    const float* k2  = (const float*)d_in[15];
    const float* kb2 = (const float*)d_in[16];
    const float* k3  = (const float*)d_in[17];
    const float* kb3 = (const float*)d_in[18];
    float* out = (float*)d_out;

    float *stacked, *y, *ytmp, *sbase, *h1, *h2, *apA, *apB, *gam, *bet;
    cudaGetSymbolAddress((void**)&stacked, g_stacked);
    cudaGetSymbolAddress((void**)&y,       g_y);
    cudaGetSymbolAddress((void**)&ytmp,    g_ytmp);
    cudaGetSymbolAddress((void**)&sbase,   g_s);
    cudaGetSymbolAddress((void**)&h1,      g_h1);
    cudaGetSymbolAddress((void**)&h2,      g_h2);
    cudaGetSymbolAddress((void**)&apA,     g_apA);
    cudaGetSymbolAddress((void**)&apB,     g_apB);
    cudaGetSymbolAddress((void**)&gam,     g_gamma);
    cudaGetSymbolAddress((void**)&bet,     g_beta);
    float* s[6];
    for (int i = 0; i < 6; i++) s[i] = sbase + (size_t)i * NTOT;

    const int SMEMB = (64*68 + 64*192) * sizeof(float);  // 66560
    cudaFuncSetAttribute(conv_k<CS,HD,true,true>,   cudaFuncAttributeMaxDynamicSharedMemorySize, SMEMB);
    cudaFuncSetAttribute(conv_k<HD,HD,false,true>,  cudaFuncAttributeMaxDynamicSharedMemorySize, SMEMB);
    cudaFuncSetAttribute(conv_k<HD,CS,false,false>, cudaFuncAttributeMaxDynamicSharedMemorySize, SMEMB);

    // ---- wavelet decomposition ----
    cpx_k<<<NCL/256, 256>>>(x);
    temb_k<<<NT, 128>>>(tw1, tb1, tw2, tb2, cw, cb);

    maxred_k<<<B*C, 256>>>(x);
    dywan_k<<<1, 256>>>(sw1, sb1, sw2, sb2, sw3, sb3);
    wconv_k<<<NCL/256, 256>>>(x, apA, 0);

    maxred_k<<<B*C, 256>>>(apA);
    dywan_k<<<1, 256>>>(sw1, sb1, sw2, sb2, sw3, sb3);
    wconv_k<<<NCL/256, 256>>>(apA, apB, 1);

    maxred_k<<<B*C, 256>>>(apB);
    dywan_k<<<1, 256>>>(sw1, sb1, sw2, sb2, sw3, sb3);
    wconv_k<<<NCL/256, 256>>>(apB, apA, 2);

    cudaMemcpyAsync(y, stacked, sizeof(float)*NTOT, cudaMemcpyDeviceToDevice);

    // ---- ODE (Dormand-Prince, fixed step) ----
    auto eval = [&](float* ob, const float* ib, int tidx) {
        conv_k<CS,HD,true,true><<<dim3(32,B,1), 256, SMEMB>>>(ib, k1, kb1, h1, gam + tidx*HD, bet + tidx*HD);
        conv_k<HD,HD,false,true><<<dim3(32,B,1), 256, SMEMB>>>(h1, k2, kb2, h2, nullptr, nullptr);
        conv_k<HD,CS,false,false><<<dim3(32,B,4), 256, SMEMB>>>(h2, k3, kb3, ob, nullptr, nullptr);
    };

    const float hs = 0.25f;
    const int NB = NTOT/4/256;  // 4096
    for (int i = 0; i < 4; i++) {
        int t0 = i * 6;
        eval(s[0], y, t0 + 0);
        combine_k<1><<<NB,256>>>((float4*)ytmp, (const float4*)y, hs,
            (const float4*)s[0], 0.2f,
            nullptr,0.f, nullptr,0.f, nullptr,0.f, nullptr,0.f);
        eval(s[1], ytmp, t0 + 1);
        combine_k<2><<<NB,256>>>((float4*)ytmp, (const float4*)y, hs,
            (const float4*)s[0], (float)(3.0/40.0),
            (const float4*)s[1], (float)(9.0/40.0),
            nullptr,0.f, nullptr,0.f, nullptr,0.f);
        eval(s[2], ytmp, t0 + 2);
        combine_k<3><<<NB,256>>>((float4*)ytmp, (const float4*)y, hs,
            (const float4*)s[0], (float)(44.0/45.0),
            (const float4*)s[1], (float)(-56.0/15.0),
            (const float4*)s[2], (float)(32.0/9.0),
            nullptr,0.f, nullptr,0.f);
        eval(s[3], ytmp, t0 + 3);
        combine_k<4><<<NB,256>>>((float4*)ytmp, (const float4*)y, hs,
            (const float4*)s[0], (float)(19372.0/6561.0),
            (const float4*)s[1], (float)(-25360.0/2187.0),
            (const float4*)s[2], (float)(64448.0/6561.0),
            (const float4*)s[3], (float)(-212.0/729.0),
            nullptr,0.f);
        eval(s[4], ytmp, t0 + 4);
        combine_k<5><<<NB,256>>>((float4*)ytmp, (const float4*)y, hs,
            (const float4*)s[0], (float)(9017.0/3168.0),
            (const float4*)s[1], (float)(-355.0/33.0),
            (const float4*)s[2], (float)(46732.0/5247.0),
            (const float4*)s[3], (float)(49.0/176.0),
            (const float4*)s[4], (float)(-5103.0/18656.0));
        eval(s[5], ytmp, t0 + 5);
        combine_k<5><<<NB,256>>>((float4*)y, (const float4*)y, hs,
            (const float4*)s[0], (float)(35.0/384.0),
            (const float4*)s[2], (float)(500.0/1113.0),
            (const float4*)s[3], (float)(125.0/192.0),
            (const float4*)s[4], (float)(-2187.0/6784.0),
            (const float4*)s[5], (float)(11.0/84.0));
    }

    // ---- final dx + ecloss + outputs ----
    eval(s[0], y, 24);
    ecl1_k<<<B*64, 256>>>(s[0]);
    ecl2_k<<<1, 64>>>(out);
    perm_k<<<(4*NCL)/256, 256>>>(out);
}